// round 1
// baseline (speedup 1.0000x reference)
#include <cuda_runtime.h>
#include <math.h>

#define MEM_SIZE 512

// ---- faithful smooth-gate helpers (jax.nn.sigmoid branch structure) ----
__device__ __forceinline__ float sigm_(float z) {
    if (z >= 0.0f) {
        return 1.0f / (1.0f + expf(-z));
    } else {
        float e = expf(z);
        return e / (1.0f + e);
    }
}
__device__ __forceinline__ float silu_(float z) { return z * sigm_(z); }

// silu_threshold(x) = (silu(20x+10) - silu(20x-10)) / 20
__device__ __forceinline__ float thr_(float x) {
    float d = 20.0f * x;
    return (silu_(d + 10.0f) - silu_(d - 10.0f)) / 20.0f;
}

// read_memory collapsed: gates at integer offsets are {1, +E, -E, ~0}
__device__ __forceinline__ float read_mem5(const float* __restrict__ mem, int p, float E) {
    float c = __ldg(mem + p);
    float A = 0.0f;
    if (p - 1 >= 0)       A += __ldg(mem + p - 1);
    if (p + 1 < MEM_SIZE) A += __ldg(mem + p + 1);
    if (p - 2 >= 0)       A -= __ldg(mem + p - 2);
    if (p + 2 < MEM_SIZE) A -= __ldg(mem + p + 2);
    return c + E * A;
}

__global__ void __launch_bounds__(256)
c4moe_step_kernel(const int* __restrict__ pc,
                  const int* __restrict__ sp,
                  const int* __restrict__ bp,
                  const float* __restrict__ axp,
                  const float* __restrict__ memory,
                  float* __restrict__ out,
                  int B)
{
    int i = blockIdx.x * blockDim.x + threadIdx.x;
    if (i >= B) return;

    const float E = 2.0611536e-9f;  // fp32(exp(-20)) : eq_gate value at |diff|=1 (negated at |diff|=2)

    const float* mem = memory + (size_t)i * MEM_SIZE;

    float ax = axp[i];

    // instruction = read_memory(memory, pc); st = read_memory(memory, sp)
    float inst = read_mem5(mem, pc[i], E);
    float st   = read_mem5(mem, sp[i], E);

    // opcode = remainder(inst, 256) [numpy semantics: result in [0,256)]
    float opcode = fmodf(inst, 256.0f);
    if (opcode < 0.0f) opcode += 256.0f;
    float imm = floorf(inst / 256.0f);

    // selected = argmax over eq_gate(opcode, e) for e in 0..39.
    // opcode = integer + tiny delta -> max at nearest integer; if clamped out of
    // range the score evaluates to exactly 0 (matching ref's out*0 = 0).
    int sel = (int)rintf(opcode);
    if (sel < 0)  sel = 0;
    if (sel > 39) sel = 39;
    float ds = opcode - (float)sel;
    float score = thr_(ds + 0.5f) * thr_(0.5f - ds);

    // ax_safe = ax + eq_gate(ax,0)*0.001  (exact in fp32: only ax==0 survives rounding)
    float ax_safe = (ax == 0.0f) ? 0.001f : ax;

    float out_v;
    switch (sel) {
        case 0: out_v = imm; break;
        case 1: out_v = (float)bp[i] + imm; break;
        case 2: out_v = st + ax; break;
        case 3: out_v = st - ax; break;
        case 4: out_v = st * ax; break;  // swiglu_mul(a,b) == a*b
        case 5:
        case 6: {
            // div_expert: q counted when st - q*a + 0.5 crosses thr center at 0
            // -> q <= floor((st+0.5)/a); result 0 outside [0,63]
            float fq = floorf((st + 0.5f) / ax_safe);
            float divr = (fq >= 0.0f && fq < 64.0f) ? fq : 0.0f;
            out_v = (sel == 5) ? divr : (st - divr * ax_safe);
            break;
        }
        case 7: out_v = st * exp2f(ax); break;            // shl
        case 8: out_v = floorf(st / exp2f(ax)); break;    // shr
        case 9:
        case 10:
        case 11: {
            // extract_bits over k<16 == 16-bit integer bitwise ops on floor(st)
            int sf = ((int)floorf(st)) & 0xFFFF;
            int af = ((int)floorf(ax)) & 0xFFFF;
            int r = (sel == 9) ? (sf & af) : (sel == 10) ? (sf | af) : (sf ^ af);
            out_v = (float)r;
            break;
        }
        case 12:
        case 13: {
            float d = st - ax;
            float eqo = thr_(d + 0.5f) * thr_(0.5f - d);
            out_v = (sel == 12) ? eqo : (1.0f - eqo);
            break;
        }
        case 14: out_v = thr_(ax - st - 0.5f); break;  // gt_gate(ax, st)
        case 15: out_v = thr_(st - ax - 0.5f); break;  // gt_gate(st, ax)
        case 16: out_v = thr_(ax - st + 0.5f); break;  // ge_gate(ax, st)
        case 17: out_v = thr_(st - ax + 0.5f); break;  // ge_gate(st, ax)
        default: out_v = ax; break;                     // noop experts 18..39
    }

    out[i] = out_v * score;
}

extern "C" void kernel_launch(void* const* d_in, const int* in_sizes, int n_in,
                              void* d_out, int out_size) {
    const int*   pc  = (const int*)d_in[0];
    const int*   sp  = (const int*)d_in[1];
    const int*   bp  = (const int*)d_in[2];
    const float* ax  = (const float*)d_in[3];
    const float* mem = (const float*)d_in[4];
    float* out = (float*)d_out;
    int B = in_sizes[0];
    int threads = 256;
    int blocks = (B + threads - 1) / threads;
    c4moe_step_kernel<<<blocks, threads>>>(pc, sp, bp, ax, mem, out, B);
}